// round 17
// baseline (speedup 1.0000x reference)
#include <cuda_runtime.h>
#include <cstdint>

// CTC batch cost (Keras ctc_batch_cost, full lengths).
// B=64, T=2048, C=128 (blank=127), L=256, S=2L+1=513.
//
// R16: EXACT extended-float forward recurrence -- zero MUFU in the loop.
// alpha stored as (m, e): value = m * 2^e, m in [1,2) (0 => m=0, e=EZERO).
//   E = max3(e); s_i = 2^(e_i - E) built by bit ops (clamped at -127 -> 0);
//   sum = m0*s0 + m1*s1 + m2*s2;  v = sum * (y+eps);  renorm via exponent
//   field extraction. Pure ALU/FMA; exact float arithmetic.
// Overlapped-warp period (R14, proven): warp w lanes k hold states
// l = 26w - 6 + k; 4 time-steps per __syncthreads (step 1 from shared,
// steps 2-4 via shfl_up; lanes >= 6 stay exact and write back).
// Per-thread y register fifo (2 banks x 4 frames, 2-period LDG lead);
// no lp tables, no producer warps. 2-CTA cluster per batch; 32-state halo
// refreshed every 16 steps via st.shared::cluster + full cluster barrier
// (mail carries m and e). y_true is int32.

#define CTC_B 64
#define CTC_T 2048
#define CTC_C 128
#define CTC_L 256
#define EPSF (1e-7f)
#define LN2F (0.69314718055994530942f)
#define EZERO (-(1 << 28))

#define NTHR  352      // 11 warps
#define NETW  26
#define OVL   6
#define PADL  8
#define ANROW 304

__device__ __forceinline__ float lg2f_(float x) {
    float r; asm("lg2.approx.ftz.f32 %0, %1;" : "=f"(r) : "f"(x)); return r;
}
__device__ __forceinline__ uint32_t smem_u32_(const void* p) {
    uint32_t a;
    asm("{ .reg .u64 t; cvta.to.shared.u64 t, %1; cvt.u32.u64 %0, t; }"
        : "=r"(a) : "l"(p));
    return a;
}

__device__ __forceinline__ void f2ext_(float v, float& m, int& e) {
    uint32_t bits = __float_as_uint(v);
    e = (int)(bits >> 23) - 127;
    m = __uint_as_float((bits & 0x007fffffu) | 0x3f800000u);
    if (bits == 0u) { m = 0.f; e = EZERO; }
}

// (m0,e0) <- lse-free exact merge: (m0,e0)+(m1,e1)+(skip?(m2,e2):0), * y
__device__ __forceinline__ void ext_step_(float& m0, int& e0,
                                          float m1, int e1,
                                          float m2, int e2,
                                          float y, int skip) {
    if (!skip) { m2 = 0.f; e2 = EZERO; }
    int E  = max(e0, max(e1, e2));
    int d0 = max(e0 - E, -127);
    int d1 = max(e1 - E, -127);
    int d2 = max(e2 - E, -127);
    float s0 = __uint_as_float((uint32_t)(127 + d0) << 23);
    float s1 = __uint_as_float((uint32_t)(127 + d1) << 23);
    float s2 = __uint_as_float((uint32_t)(127 + d2) << 23);
    float sum = fmaf(m1, s1, m0 * s0);
    sum = fmaf(m2, s2, sum);
    float v = sum * y;
    uint32_t bits = __float_as_uint(v);
    int ev = (int)(bits >> 23) - 127;
    m0 = __uint_as_float((bits & 0x007fffffu) | 0x3f800000u);
    e0 = E + ev;
    if (bits == 0u) { m0 = 0.f; e0 = EZERO; }
}

__global__ __launch_bounds__(NTHR, 1) __cluster_dims__(2, 1, 1)
void ctc_forward_kernel(const int* __restrict__ y_true,
                        const float* __restrict__ y_pred,
                        float* __restrict__ out) {
    __shared__ float s_Am[2][ANROW];
    __shared__ int   s_Ae[2][ANROW];
    __shared__ float s_mailm[2][32];
    __shared__ int   s_maile[2][32];

    const int tid  = threadIdx.x;
    const int lane = tid & 31;
    const int wid  = tid >> 5;
    uint32_t rank;
    asm("mov.u32 %0, %%cluster_ctarank;" : "=r"(rank));
    const int b = blockIdx.x >> 1;

    const int*   lab = y_true + b * CTC_L;
    const float* Y   = y_pred + (size_t)b * CTC_T * CTC_C;

    const int l  = NETW * wid - OVL + lane;   // -6 .. 285
    const int li = l + PADL;
    const int s  = rank ? (l + 240) : l;

    int cls = CTC_C - 1, skip = 0;
    if (s >= 1 && (s & 1)) {
        int i = s >> 1; if (i > CTC_L - 1) i = CTC_L - 1;
        cls  = lab[i] & 127;
        skip = (s >= 3 && cls != (lab[i - 1] & 127)) ? 1 : 0;
    }
    const float* Yc = Y + cls;

    // ---- init alpha buffers to zero-value ----
    for (int i = tid; i < ANROW; i += NTHR) {
        s_Am[0][i] = 0.f;  s_Ae[0][i] = EZERO;
        s_Am[1][i] = 0.f;  s_Ae[1][i] = EZERO;
    }
    __syncthreads();

    if (rank == 0 && tid == 0) {
        float m; int e; f2ext_(Y[CTC_C - 1] + EPSF, m, e);
        s_Am[0][PADL + 0] = m;  s_Ae[0][PADL + 0] = e;
    }
    if (rank == 0 && tid == 1) {
        float m; int e; f2ext_(Y[lab[0] & 127] + EPSF, m, e);
        s_Am[0][PADL + 1] = m;  s_Ae[0][PADL + 1] = e;
    }

    // remote mailbox addresses (rank0 senders, states 240..271)
    uint32_t rm0 = 0, rm1 = 0, re0 = 0, re1 = 0;
    if (rank == 0 && tid >= 240 && tid < 272) {
        uint32_t am0 = smem_u32_(&s_mailm[0][tid - 240]);
        uint32_t am1 = smem_u32_(&s_mailm[1][tid - 240]);
        uint32_t ae0 = smem_u32_(&s_maile[0][tid - 240]);
        uint32_t ae1 = smem_u32_(&s_maile[1][tid - 240]);
        asm("mapa.shared::cluster.u32 %0, %1, %2;" : "=r"(rm0) : "r"(am0), "r"(1));
        asm("mapa.shared::cluster.u32 %0, %1, %2;" : "=r"(rm1) : "r"(am1), "r"(1));
        asm("mapa.shared::cluster.u32 %0, %1, %2;" : "=r"(re0) : "r"(ae0), "r"(1));
        asm("mapa.shared::cluster.u32 %0, %1, %2;" : "=r"(re1) : "r"(ae1), "r"(1));
    }

    // y fifo: bank0 = frames 1..4, bank1 = frames 5..8 (y+eps)
    float q[8];
#pragma unroll
    for (int j = 0; j < 8; j++) q[j] = Yc[(1 + j) << 7] + EPSF;
    __syncthreads();

#define QRELOAD(p, BK) do {                                                    \
        int f0 = 4 * (p) + 9, f1 = f0 + 1, f2 = f0 + 2, f3 = f0 + 3;           \
        if (f0 > 2047) f0 = 2047;  if (f1 > 2047) f1 = 2047;                   \
        if (f2 > 2047) f2 = 2047;  if (f3 > 2047) f3 = 2047;                   \
        q[(BK) * 4 + 0] = Yc[f0 << 7] + EPSF;                                  \
        q[(BK) * 4 + 1] = Yc[f1 << 7] + EPSF;                                  \
        q[(BK) * 4 + 2] = Yc[f2 << 7] + EPSF;                                  \
        q[(BK) * 4 + 3] = Yc[f3 << 7] + EPSF;                                  \
    } while (0)

#define SHFLN()  do {                                                          \
        m1 = __shfl_up_sync(0xffffffffu, m0, 1);                               \
        e1 = __shfl_up_sync(0xffffffffu, e0, 1);                               \
        m2 = __shfl_up_sync(0xffffffffu, m0, 2);                               \
        e2 = __shfl_up_sync(0xffffffffu, e0, 2);                               \
    } while (0)

#define PERIOD(p, H, BK) do {                                                  \
        const float* __restrict__ Amr = s_Am[(H)];                             \
        const int*   __restrict__ Aer = s_Ae[(H)];                             \
        float* __restrict__ Amw = s_Am[1 - (H)];                               \
        int*   __restrict__ Aew = s_Ae[1 - (H)];                               \
        float m0 = Amr[li];      int e0 = Aer[li];                             \
        float m1 = Amr[li - 1];  int e1 = Aer[li - 1];                         \
        float m2 = Amr[li - 2];  int e2 = Aer[li - 2];                         \
        ext_step_(m0, e0, m1, e1, m2, e2, q[(BK) * 4 + 0], skip);              \
        SHFLN();                                                               \
        ext_step_(m0, e0, m1, e1, m2, e2, q[(BK) * 4 + 1], skip);              \
        SHFLN();                                                               \
        ext_step_(m0, e0, m1, e1, m2, e2, q[(BK) * 4 + 2], skip);              \
        SHFLN();                                                               \
        ext_step_(m0, e0, m1, e1, m2, e2, q[(BK) * 4 + 3], skip);              \
        if (lane >= OVL) { Amw[li] = m0;  Aew[li] = e0; }                      \
        QRELOAD(p, BK);                                                        \
        __syncthreads();                                                       \
    } while (0)

#define XCHG(p) do { if (((p) & 3) == 3) {                                     \
        int m_   = ((p) + 1) >> 2;                                             \
        int buf_ = m_ & 1;                                                     \
        float* Amw_ = s_Am[1 - ((p) & 1)];                                     \
        int*   Aew_ = s_Ae[1 - ((p) & 1)];                                     \
        if (rank == 0 && tid >= 240 && tid < 272) {                            \
            float vm_ = Amw_[tid + PADL];                                      \
            int   ve_ = Aew_[tid + PADL];                                      \
            uint32_t ram_ = buf_ ? rm1 : rm0;                                  \
            uint32_t rae_ = buf_ ? re1 : re0;                                  \
            asm volatile("st.shared::cluster.f32 [%0], %1;"                    \
                         :: "r"(ram_), "f"(vm_) : "memory");                   \
            asm volatile("st.shared::cluster.u32 [%0], %1;"                    \
                         :: "r"(rae_), "r"((uint32_t)ve_) : "memory");         \
        }                                                                      \
        asm volatile("barrier.cluster.arrive.aligned;" ::: "memory");          \
        asm volatile("barrier.cluster.wait.aligned;"   ::: "memory");          \
        if (rank == 1 && tid < 32) {                                           \
            Amw_[tid + PADL] = s_mailm[buf_][tid];                             \
            Aew_[tid + PADL] = s_maile[buf_][tid];                             \
        }                                                                      \
        __syncthreads();                                                       \
    } } while (0)

    // main: 511 full periods (t = 1..2044), then a 3-step tail (2045..2047)
    for (int p = 0; p < 510; p += 2) {
        PERIOD(p,     0, 0);
        XCHG(p);
        PERIOD(p + 1, 1, 1);
        XCHG(p + 1);
    }
    PERIOD(510, 0, 0);   // (510 & 3) == 2 -> no exchange

    // tail period p=511 (H=1, bank1): 3 steps
    {
        const float* __restrict__ Amr = s_Am[1];
        const int*   __restrict__ Aer = s_Ae[1];
        float* __restrict__ Amw = s_Am[0];
        int*   __restrict__ Aew = s_Ae[0];
        float m0 = Amr[li];      int e0 = Aer[li];
        float m1 = Amr[li - 1];  int e1 = Aer[li - 1];
        float m2 = Amr[li - 2];  int e2 = Aer[li - 2];
        ext_step_(m0, e0, m1, e1, m2, e2, q[4], skip);
        SHFLN();
        ext_step_(m0, e0, m1, e1, m2, e2, q[5], skip);
        SHFLN();
        ext_step_(m0, e0, m1, e1, m2, e2, q[6], skip);
        if (lane >= OVL) { Amw[li] = m0;  Aew[li] = e0; }
        __syncthreads();
    }

#undef PERIOD
#undef XCHG
#undef SHFLN
#undef QRELOAD

    // final: states 511 (l=271) and 512 (l=272) in buffer 0
    if (rank == 1 && tid == 0) {
        float am = s_Am[0][272 + PADL];  int ae = s_Ae[0][272 + PADL];
        float cm = s_Am[0][271 + PADL];  int ce = s_Ae[0][271 + PADL];
        int E  = max(ae, ce);
        int da = max(ae - E, -127), dc = max(ce - E, -127);
        float v = am * __uint_as_float((uint32_t)(127 + da) << 23)
                + cm * __uint_as_float((uint32_t)(127 + dc) << 23);
        out[b] = -((float)E + lg2f_(v)) * LN2F;
    }

    asm volatile("barrier.cluster.arrive.aligned;" ::: "memory");
    asm volatile("barrier.cluster.wait.aligned;"   ::: "memory");
}

extern "C" void kernel_launch(void* const* d_in, const int* in_sizes, int n_in,
                              void* d_out, int out_size) {
    const int*   y_true;
    const float* y_pred;
    if (in_sizes[0] == CTC_B * CTC_L) {
        y_true = (const int*)d_in[0];
        y_pred = (const float*)d_in[1];
    } else {
        y_true = (const int*)d_in[1];
        y_pred = (const float*)d_in[0];
    }
    float* out = (float*)d_out;

    ctc_forward_kernel<<<2 * CTC_B, NTHR>>>(y_true, y_pred, out);
}